// round 14
// baseline (speedup 1.0000x reference)
#include <cuda_runtime.h>
#include <mma.h>
#include <math.h>
#include <stdint.h>

using namespace nvcuda;

// ---------------- problem constants ----------------
#define BB   8
#define LL   1024
#define DMD  256
#define NLY  4
#define EDD  512
#define NSS  16
#define DCC  4
#define RKK  16
#define CDD  64
#define QQ   2
#define BL   (BB*LL)          // 8192 rows
#define NCH  16               // scan chunks
#define CHL  (LL/NCH)         // 64 steps per chunk
#define XDS  64               // padded row stride of xd buffer (48 -> 64)
#define NXP  48               // xp_w cols
#define EG   (EDD/128)        // e-groups per scan kernel = 4

// ---------------- scratch ----------------
__device__ __align__(256) float g_x [BL*DMD];
__device__ __align__(256) float g_xn[BL*DMD];
__device__ __align__(256) float g_xz[BL*2*EDD];
__device__ __align__(256) float g_xs[BL*EDD];
__device__ __align__(256) float g_y [BL*EDD];
__device__ __align__(256) float g_xd[BL*XDS];
__device__ __align__(256) float g_ss[NLY*BB*2*DMD];
__device__ __align__(256) float g_aP[BB*NCH*NSS*EDD];
__device__ __align__(256) float g_bL[BB*NCH*NSS*EDD];
// tf32-pre-rounded weight copies
__device__ __align__(256) float g_wrI[NLY*DMD*2*EDD];
__device__ __align__(256) float g_wrX[NLY*EDD*NXP];
__device__ __align__(256) float g_wrO[NLY*EDD*DMD];
// scan handshake + epilogue counters
__device__ unsigned int g_epoch = 0;
__device__ unsigned int g_sflag[EG*BB*NCH];   // per (g,b,c)
__device__ unsigned int g_cnt[BL/128];        // per out-GEMM row-block

// ---------------- cp.async helpers ----------------
__device__ __forceinline__ void cp16(void* smem_dst, const void* gsrc, int src_bytes)
{
    uint32_t d = (uint32_t)__cvta_generic_to_shared(smem_dst);
    asm volatile("cp.async.cg.shared.global [%0], [%1], 16, %2;\n"
                 :: "r"(d), "l"(gsrc), "r"(src_bytes));
}
__device__ __forceinline__ void cp_commit() { asm volatile("cp.async.commit_group;\n"); }
template<int NG> __device__ __forceinline__ void cp_wait()
{ asm volatile("cp.async.wait_group %0;\n" :: "n"(NG)); }

__device__ __forceinline__ float rtf(float x) { return wmma::__float_to_tf32(x); }

// rv^(n+1) for n=0..15, log-depth
__device__ __forceinline__ void powers16(float rv, float* pw)
{
    pw[0] = rv;
    pw[1] = rv*rv;
    pw[2] = pw[1]*rv;
    pw[3] = pw[1]*pw[1];
    pw[4] = pw[3]*pw[0];
    pw[5] = pw[3]*pw[1];
    pw[6] = pw[3]*pw[2];
    pw[7] = pw[3]*pw[3];
    #pragma unroll
    for (int n = 0; n < 7; n++) pw[8+n] = pw[7]*pw[n];
    pw[15] = pw[7]*pw[7];
}

__device__ __forceinline__ void softplus_rd(float raw, float& dlt, float& rv)
{
    if (raw > 15.0f) { dlt = raw; rv = __expf(-raw); }
    else {
        float ex = __expf(raw);
        rv  = 1.0f/(1.0f + ex);
        dlt = log1pf(ex);
    }
}

// ---------------- prologue: weight rounding + embed + cond/modulation (one kernel) ----------------
#define PRO_EMB  (BL*DMD/256)          // 8192 blocks
#define PRO_RND  1024
#define PRO_CSS  (NLY*BB*2*DMD/256)    // 64 blocks
__global__ void k_prologue(const int* __restrict__ tokens,
                           const float* __restrict__ tok_embed,
                           const float* __restrict__ pos_embed,
                           const float* __restrict__ in_w,
                           const float* __restrict__ xp_w,
                           const float* __restrict__ out_w,
                           const float* __restrict__ T,
                           const float* __restrict__ tw1, const float* __restrict__ tb1,
                           const float* __restrict__ tw2, const float* __restrict__ tb2,
                           const float* __restrict__ apw, const float* __restrict__ apb)
{
    int bid = blockIdx.x;
    int tid = threadIdx.x;
    if (bid < PRO_EMB) {
        int idx = bid*256 + tid;
        int d  = idx % DMD;
        int bl = idx / DMD;
        int l  = bl % LL;
        int b  = bl / LL;
        float v = pos_embed[l*DMD + d];
        if (l > 0) {
            int tok = tokens[b*LL + l - 1];
            v += tok_embed[tok*DMD + d];
        }
        g_x[idx] = v;
        return;
    }
    if (bid < PRO_EMB + PRO_RND) {
        int rb = bid - PRO_EMB;
        if (rb == 0 && tid == 0) atomicAdd(&g_epoch, 1u);
        const int nI = NLY*DMD*2*EDD;
        const int nX = NLY*EDD*NXP;
        const int nO = NLY*EDD*DMD;
        int stride = PRO_RND*256;
        int t0 = rb*256 + tid;
        for (int i = t0; i < nI; i += stride) g_wrI[i] = rtf(in_w[i]);
        for (int i = t0; i < nX; i += stride) g_wrX[i] = rtf(xp_w[i]);
        for (int i = t0; i < nO; i += stride) g_wrO[i] = rtf(out_w[i]);
        return;
    }
    // cond + ss
    __shared__ float hs[BB*CDD];
    __shared__ float cond[BB*CDD];
    #pragma unroll
    for (int q = 0; q < 2; q++) {
        int i2 = tid + q*256;
        int b = i2 / CDD, c = i2 % CDD;
        float u = T[b]*tw1[c] + tb1[c];
        hs[i2] = 0.5f*u*(1.0f + erff(u*0.70710678118654752440f));
    }
    __syncthreads();
    #pragma unroll
    for (int q = 0; q < 2; q++) {
        int i2 = tid + q*256;
        int b = i2 / CDD, c = i2 % CDD;
        float acc = tb2[c];
        #pragma unroll 8
        for (int k = 0; k < CDD; k++) acc += hs[b*CDD + k]*tw2[k*CDD + c];
        cond[i2] = acc;
    }
    __syncthreads();
    int idx = (bid - PRO_EMB - PRO_RND)*256 + tid;   // 0..16383
    int j  = idx % (2*DMD);
    int ib = idx / (2*DMD);
    int b  = ib % BB;
    int i  = ib / BB;
    float acc = apb[i*2*DMD + j];
    #pragma unroll 8
    for (int c = 0; c < CDD; c++)
        acc += cond[b*CDD + c] * apw[((size_t)i*CDD + c)*2*DMD + j];
    g_ss[((size_t)i*BB + b)*2*DMD + j] = acc;
}

// ---------------- standalone AdaLN (layer 0 only), tf32-rounded output ----------------
__global__ void k_ln(const float* __restrict__ x, const float* __restrict__ gam,
                     const float* __restrict__ bet, const float* __restrict__ ss,
                     float* __restrict__ out)
{
    int tid = threadIdx.x;              // 256
    int rl  = tid >> 6;
    int lw  = tid & 63;
    int row = blockIdx.x*4 + rl;
    float4 v = reinterpret_cast<const float4*>(x + (size_t)row*DMD)[lw];
    float s  = v.x+v.y+v.z+v.w;
    float s2 = v.x*v.x+v.y*v.y+v.z*v.z+v.w*v.w;
    #pragma unroll
    for (int o = 16; o; o >>= 1) {
        s  += __shfl_xor_sync(0xffffffffu, s,  o);
        s2 += __shfl_xor_sync(0xffffffffu, s2, o);
    }
    __shared__ float sh1[4][2], sh2[4][2];
    if ((lw & 31) == 0) { sh1[rl][lw>>5] = s; sh2[rl][lw>>5] = s2; }
    __syncthreads();
    float tot  = sh1[rl][0] + sh1[rl][1];
    float tot2 = sh2[rl][0] + sh2[rl][1];
    float mean = tot * (1.0f/DMD);
    float var  = tot2 * (1.0f/DMD) - mean*mean;
    float inv  = rsqrtf(var + 1e-5f);
    float4 g  = reinterpret_cast<const float4*>(gam)[lw];
    float4 bb = reinterpret_cast<const float4*>(bet)[lw];
    float4 o4;
    o4.x = (v.x-mean)*inv*g.x + bb.x;
    o4.y = (v.y-mean)*inv*g.y + bb.y;
    o4.z = (v.z-mean)*inv*g.z + bb.z;
    o4.w = (v.w-mean)*inv*g.w + bb.w;
    int b = row / LL;
    float4 sc = reinterpret_cast<const float4*>(ss + (size_t)b*2*DMD)[lw];
    float4 sh = reinterpret_cast<const float4*>(ss + (size_t)b*2*DMD + DMD)[lw];
    o4.x = rtf(fmaf(sc.x, o4.x, o4.x) + sh.x);
    o4.y = rtf(fmaf(sc.y, o4.y, o4.y) + sh.y);
    o4.z = rtf(fmaf(sc.z, o4.z, o4.z) + sh.z);
    o4.w = rtf(fmaf(sc.w, o4.w, o4.w) + sh.w);
    reinterpret_cast<float4*>(out + (size_t)row*DMD)[lw] = o4;
}

// ---------------- pipelined TF32 GEMM (R8 config, inputs pre-rounded) ----------------
template<int BM, int BN, int BK, int WR, int WC>
__global__ void __launch_bounds__(WR*WC*32)
gemm_tf32p(const float* __restrict__ A, const float* __restrict__ W,
           float* __restrict__ C, int M, int Nw, int K, int ldc, int accum)
{
    constexpr int NT  = WR*WC*32;
    constexpr int WM  = BM/WR, WN = BN/WC;
    constexpr int MI  = WM/16, NI = WN/16;
    constexpr int LDA = BK + 4;
    constexpr int LDB = BN + 4;
    extern __shared__ float sm[];
    float* sA = sm;
    float* sB = sm + 2*BM*LDA;

    const int tid  = threadIdx.x;
    const int warp = tid >> 5;
    const int wy   = warp / WC;
    const int wx   = warp % WC;
    const int row0 = blockIdx.y * BM;
    const int col0 = blockIdx.x * BN;

    wmma::fragment<wmma::accumulator, 16,16,8, float> acc[MI][NI];
    #pragma unroll
    for (int i = 0; i < MI; i++)
        #pragma unroll
        for (int j = 0; j < NI; j++) wmma::fill_fragment(acc[i][j], 0.0f);

    auto load_tiles = [&](int st, int k0) {
        float* dA = sA + st*BM*LDA;
        float* dB = sB + st*BK*LDB;
        #pragma unroll
        for (int f = tid; f < BM*(BK/4); f += NT) {
            int r = f / (BK/4);
            int c = (f % (BK/4)) * 4;
            cp16(&dA[r*LDA + c], A + (size_t)(row0+r)*K + k0 + c, 16);
        }
        #pragma unroll
        for (int f = tid; f < BK*(BN/4); f += NT) {
            int r = f / (BN/4);
            int c = (f % (BN/4)) * 4;
            int col = col0 + c;
            int sb  = (col < Nw) ? 16 : 0;
            const float* src = W + (size_t)(k0+r)*Nw + (sb ? col : 0);
            cp16(&dB[r*LDB + c], src, sb);
        }
    };

    const int nt = K / BK;
    int stage = 0;
    load_tiles(0, 0);
    cp_commit();

    for (int t = 0; t < nt; t++) {
        if (t + 1 < nt) {
            load_tiles(stage ^ 1, (t+1)*BK);
            cp_commit();
            cp_wait<1>();
        } else {
            cp_wait<0>();
        }
        __syncthreads();
        const float* cA = sA + stage*BM*LDA;
        const float* cB = sB + stage*BK*LDB;
        #pragma unroll
        for (int kk = 0; kk < BK/8; kk++) {
            wmma::fragment<wmma::matrix_a, 16,16,8, wmma::precision::tf32, wmma::row_major> af[MI];
            wmma::fragment<wmma::matrix_b, 16,16,8, wmma::precision::tf32, wmma::row_major> bf[NI];
            #pragma unroll
            for (int i = 0; i < MI; i++)
                wmma::load_matrix_sync(af[i], &cA[(wy*WM + i*16)*LDA + kk*8], LDA);
            #pragma unroll
            for (int j = 0; j < NI; j++)
                wmma::load_matrix_sync(bf[j], &cB[(kk*8)*LDB + wx*WN + j*16], LDB);
            #pragma unroll
            for (int i = 0; i < MI; i++)
                #pragma unroll
                for (int j = 0; j < NI; j++)
                    wmma::mma_sync(acc[i][j], af[i], bf[j], acc[i][j]);
        }
        __syncthreads();
        stage ^= 1;
    }

    #pragma unroll
    for (int i = 0; i < MI; i++) {
        #pragma unroll
        for (int j = 0; j < NI; j++) {
            float* cptr = C + (size_t)(row0 + wy*WM + i*16)*ldc + col0 + wx*WN + j*16;
            if (accum) {
                wmma::fragment<wmma::accumulator, 16,16,8, float> o;
                wmma::load_matrix_sync(o, cptr, ldc, wmma::mem_row_major);
                #pragma unroll
                for (int e = 0; e < o.num_elements; e++) acc[i][j].x[e] += o.x[e];
            }
            wmma::store_matrix_sync(cptr, acc[i][j], ldc, wmma::mem_row_major);
        }
    }
}

// ---------------- out-GEMM with last-CTA fused LN epilogue ----------------
// BM=128, BN=128, K=512, grid (2, 64), 256 thr. mode 1: AdaLN->xn. mode 2: final LN+head->out.
__global__ void __launch_bounds__(256)
gemm_outf(const float* __restrict__ A, const float* __restrict__ W,
          float* __restrict__ C, float* __restrict__ xn,
          const float* __restrict__ ss,  const float* __restrict__ gam,
          const float* __restrict__ bet, const float* __restrict__ fg,
          const float* __restrict__ fb,  const float* __restrict__ hw,
          const float* __restrict__ hb,  float* __restrict__ outp, int mode)
{
    constexpr int BM=128, BN=128, BK=32, NT=256, WR=2, WC=4;
    constexpr int WM=BM/WR, WN=BN/WC, MI=WM/16, NI=WN/16;
    constexpr int LDA=BK+4, LDB=BN+4;
    constexpr int K=EDD, Nw=DMD, ldc=DMD, nt=K/BK;
    extern __shared__ float sm[];
    float* sA = sm;
    float* sB = sm + 2*BM*LDA;

    const int tid  = threadIdx.x;
    const int warp = tid >> 5;
    const int lane = tid & 31;
    const int wy   = warp / WC;
    const int wx   = warp % WC;
    const int row0 = blockIdx.y * BM;
    const int col0 = blockIdx.x * BN;

    wmma::fragment<wmma::accumulator, 16,16,8, float> acc[MI][NI];
    #pragma unroll
    for (int i = 0; i < MI; i++)
        #pragma unroll
        for (int j = 0; j < NI; j++) wmma::fill_fragment(acc[i][j], 0.0f);

    auto load_tiles = [&](int st, int k0) {
        float* dA = sA + st*BM*LDA;
        float* dB = sB + st*BK*LDB;
        #pragma unroll
        for (int f = tid; f < BM*(BK/4); f += NT) {
            int r = f / (BK/4);
            int c = (f % (BK/4)) * 4;
            cp16(&dA[r*LDA + c], A + (size_t)(row0+r)*K + k0 + c, 16);
        }
        #pragma unroll
        for (int f = tid; f < BK*(BN/4); f += NT) {
            int r = f / (BN/4);
            int c = (f % (BN/4)) * 4;
            cp16(&dB[r*LDB + c], W + (size_t)(k0+r)*Nw + col0 + c, 16);
        }
    };

    int stage = 0;
    load_tiles(0, 0);
    cp_commit();
    for (int t = 0; t < nt; t++) {
        if (t + 1 < nt) {
            load_tiles(stage ^ 1, (t+1)*BK);
            cp_commit();
            cp_wait<1>();
        } else {
            cp_wait<0>();
        }
        __syncthreads();
        const float* cA = sA + stage*BM*LDA;
        const float* cB = sB + stage*BK*LDB;
        #pragma unroll
        for (int kk = 0; kk < BK/8; kk++) {
            wmma::fragment<wmma::matrix_a, 16,16,8, wmma::precision::tf32, wmma::row_major> af[MI];
            wmma::fragment<wmma::matrix_b, 16,16,8, wmma::precision::tf32, wmma::row_major> bf[NI];
            #pragma unroll
            for (int i = 0; i < MI; i++)
                wmma::load_matrix_sync(af[i], &cA[(wy*WM + i*16)*LDA + kk*8], LDA);
            #pragma unroll
            for (int j = 0; j < NI; j++)
                wmma::load_matrix_sync(bf[j], &cB[(kk*8)*LDB + wx*WN + j*16], LDB);
            #pragma unroll
            for (int i = 0; i < MI; i++)
                #pragma unroll
                for (int j = 0; j < NI; j++)
                    wmma::mma_sync(acc[i][j], af[i], bf[j], acc[i][j]);
        }
        __syncthreads();
        stage ^= 1;
    }

    // residual accumulate into x
    #pragma unroll
    for (int i = 0; i < MI; i++) {
        #pragma unroll
        for (int j = 0; j < NI; j++) {
            float* cptr = C + (size_t)(row0 + wy*WM + i*16)*ldc + col0 + wx*WN + j*16;
            wmma::fragment<wmma::accumulator, 16,16,8, float> o;
            wmma::load_matrix_sync(o, cptr, ldc, wmma::mem_row_major);
            #pragma unroll
            for (int e = 0; e < o.num_elements; e++) acc[i][j].x[e] += o.x[e];
            wmma::store_matrix_sync(cptr, acc[i][j], ldc, wmma::mem_row_major);
        }
    }

    // ---- last-CTA-per-rowblock LN epilogue ----
    __threadfence();
    __shared__ unsigned int lastf;
    if (tid == 0) {
        unsigned int v = atomicAdd(&g_cnt[blockIdx.y], 1u) + 1u;
        lastf = ((v & 1u) == 0u);    // exactly 2 arrivals per rowblock per launch
    }
    __syncthreads();
    if (!lastf) return;
    __threadfence();

    // warp w handles rows w*16 .. w*16+15; 32 lanes x 2 float4 per row
    #pragma unroll 1
    for (int r16 = 0; r16 < 16; r16++) {
        int rloc = warp*16 + r16;
        int row  = row0 + rloc;
        float4 xa = reinterpret_cast<const float4*>(C + (size_t)row*DMD)[lane];
        float4 xb = reinterpret_cast<const float4*>(C + (size_t)row*DMD + 128)[lane];
        float s  = xa.x+xa.y+xa.z+xa.w + xb.x+xb.y+xb.z+xb.w;
        float s2 = xa.x*xa.x+xa.y*xa.y+xa.z*xa.z+xa.w*xa.w
                 + xb.x*xb.x+xb.y*xb.y+xb.z*xb.z+xb.w*xb.w;
        #pragma unroll
        for (int o = 16; o; o >>= 1) {
            s  += __shfl_xor_sync(0xffffffffu, s,  o);
            s2 += __shfl_xor_sync(0xffffffffu, s2, o);
        }
        float mean = s * (1.0f/DMD);
        float var  = s2 * (1.0f/DMD) - mean*mean;
        float inv  = rsqrtf(var + 1e-5f);
        if (mode == 1) {
            int b = row / LL;
            float4 ga = reinterpret_cast<const float4*>(gam)[lane];
            float4 gb = reinterpret_cast<const float4*>(gam + 128)[lane];
            float4 ba = reinterpret_cast<const float4*>(bet)[lane];
            float4 bb = reinterpret_cast<const float4*>(bet + 128)[lane];
            const float* ssb = ss + (size_t)b*2*DMD;
            float4 sca = reinterpret_cast<const float4*>(ssb)[lane];
            float4 scb = reinterpret_cast<const float4*>(ssb + 128)[lane];
            float4 sha = reinterpret_cast<const float4*>(ssb + DMD)[lane];
            float4 shb = reinterpret_cast<const float4*>(ssb + DMD + 128)[lane];
            float4 oa, ob;
            oa.x = (xa.x-mean)*inv*ga.x + ba.x;
            oa.y = (xa.y-mean)*inv*ga.y + ba.y;
            oa.z = (xa.z-mean)*inv*ga.z + ba.z;
            oa.w = (xa.w-mean)*inv*ga.w + ba.w;
            ob.x = (xb.x-mean)*inv*gb.x + bb.x;
            ob.y = (xb.y-mean)*inv*gb.y + bb.y;
            ob.z = (xb.z-mean)*inv*gb.z + bb.z;
            ob.w = (xb.w-mean)*inv*gb.w + bb.w;
            oa.x = rtf(fmaf(sca.x, oa.x, oa.x) + sha.x);
            oa.y = rtf(fmaf(sca.y, oa.y, oa.y) + sha.y);
            oa.z = rtf(fmaf(sca.z, oa.z, oa.z) + sha.z);
            oa.w = rtf(fmaf(sca.w, oa.w, oa.w) + sha.w);
            ob.x = rtf(fmaf(scb.x, ob.x, ob.x) + shb.x);
            ob.y = rtf(fmaf(scb.y, ob.y, ob.y) + shb.y);
            ob.z = rtf(fmaf(scb.z, ob.z, ob.z) + shb.z);
            ob.w = rtf(fmaf(scb.w, ob.w, ob.w) + shb.w);
            reinterpret_cast<float4*>(xn + (size_t)row*DMD)[lane] = oa;
            reinterpret_cast<float4*>(xn + (size_t)row*DMD + 128)[lane] = ob;
        } else {
            float4 ga = reinterpret_cast<const float4*>(fg)[lane];
            float4 gb = reinterpret_cast<const float4*>(fg + 128)[lane];
            float4 ba = reinterpret_cast<const float4*>(fb)[lane];
            float4 bb = reinterpret_cast<const float4*>(fb + 128)[lane];
            float o0 = (xa.x-mean)*inv*ga.x + ba.x;
            float o1 = (xa.y-mean)*inv*ga.y + ba.y;
            float o2 = (xa.z-mean)*inv*ga.z + ba.z;
            float o3 = (xa.w-mean)*inv*ga.w + ba.w;
            float o4 = (xb.x-mean)*inv*gb.x + bb.x;
            float o5 = (xb.y-mean)*inv*gb.y + bb.y;
            float o6 = (xb.z-mean)*inv*gb.z + bb.z;
            float o7 = (xb.w-mean)*inv*gb.w + bb.w;
            const float2* hw2 = reinterpret_cast<const float2*>(hw);
            int c0 = lane*4, c1 = 128 + lane*4;
            float2 wa0 = hw2[c0+0], wa1 = hw2[c0+1], wa2 = hw2[c0+2], wa3 = hw2[c0+3];
            float2 wb0 = hw2[c1+0], wb1 = hw2[c1+1], wb2 = hw2[c1+2], wb3 = hw2[c1+3];
            float p0 = o0*wa0.x + o1*wa1.x + o2*wa2.x + o3*wa3.x
                     + o4*wb0.x + o5*wb1.x + o6*wb2.x + o7*wb3.x;
            float p1 = o0*wa0.y + o1*wa1.y + o2*wa2.y + o3*wa3.y
                     + o4*wb0.y + o5*wb1.y + o6*wb2.y + o7*wb3.y;
            #pragma unroll
            for (int o = 16; o; o >>= 1) {
                p0 += __shfl_xor_sync(0xffffffffu, p0, o);
                p1 += __shfl_xor_sync(0xffffffffu, p1, o);
            }
            if (lane == 0) {
                outp[(size_t)row*QQ + 0] = p0 + hb[0];
                outp[(size_t)row*QQ + 1] = p1 + hb[1];
            }
        }
    }
}

// ---------------- depthwise causal conv + bias + silu, 4 timesteps/thread ----------------
__global__ void k_conv(const float* __restrict__ w, const float* __restrict__ cb)
{
    int idx = blockIdx.x*256 + threadIdx.x;         // (BL/4)*ED
    if (idx >= (BL/4)*EDD) return;
    int e  = idx % EDD;
    int g  = idx / EDD;
    int b  = g / (LL/4);
    int l0 = (g % (LL/4)) * 4;
    size_t bl0 = (size_t)(b*LL + l0);
    const float* base = g_xz + bl0*(2*EDD) + e;
    float4 wv = *reinterpret_cast<const float4*>(w + (size_t)e*DCC);
    float cbe = cb[e];
    float v[7];
    #pragma unroll
    for (int j = 0; j < 3; j++)
        v[j] = (l0 + j >= 3) ? base[(j-3)*(2*EDD)] : 0.0f;
    #pragma unroll
    for (int j = 3; j < 7; j++)
        v[j] = base[(j-3)*(2*EDD)];
    float* outp = g_xs + bl0*EDD + e;
    #pragma unroll
    for (int i = 0; i < 4; i++) {
        float acc = cbe + wv.x*v[i] + wv.y*v[i+1] + wv.z*v[i+2] + wv.w*v[i+3];
        float sg = 1.0f/(1.0f + __expf(-acc));
        outp[(size_t)i*EDD] = rtf(acc * sg);
    }
}

// ---------------- fused scan: summary + flag + prefix combine + replay ----------------
__global__ void k_scanF(const float* __restrict__ Alog, const float* __restrict__ dtw,
                        const float* __restrict__ dtb,  const float* __restrict__ Dp,
                        int layer)
{
    int g = blockIdx.x;
    int c = blockIdx.y;
    int b = blockIdx.z;
    int e = g*128 + threadIdx.x;
    __shared__ float S[CHL][48];
    for (int f = threadIdx.x; f < CHL*12; f += 128) {
        int t = f / 12, q = (f % 12)*4;
        *reinterpret_cast<float4*>(&S[t][q]) =
            *reinterpret_cast<const float4*>(&g_xd[((size_t)(b*LL + c*CHL + t))*XDS + q]);
    }
    float wreg[RKK];
    #pragma unroll
    for (int k = 0; k < RKK; k++) wreg[k] = dtw[(size_t)k*EDD + e];
    float dtbe = dtb[e];
    float a[NSS];
    bool fast = true;
    #pragma unroll
    for (int n = 0; n < NSS; n++) {
        a[n] = expf(Alog[(size_t)e*NSS + n]);
        if (fabsf(a[n] - (float)(n+1)) > 1e-4f*(float)(n+1)) fast = false;
    }
    unsigned int target = (g_epoch - 1u)*NLY + (unsigned)layer + 1u;
    unsigned int* flg = &g_sflag[(g*BB + b)*NCH];
    __syncthreads();

    const float* xp = g_xs + ((size_t)(b*LL + c*CHL))*EDD + e;
    size_t ob = ((size_t)(b*NCH + c)*NSS)*EDD + e;

    float h[NSS];
    #pragma unroll
    for (int n = 0; n < NSS; n++) h[n] = 0.0f;
    if (fast) {
        float rprod = 1.0f;
        for (int t = 0; t < CHL; t++) {
            float raw = dtbe;
            #pragma unroll
            for (int k = 0; k < RKK; k++) raw = fmaf(S[t][k], wreg[k], raw);
            float dlt, rv;
            softplus_rd(raw, dlt, rv);
            float pv = dlt * xp[(size_t)t*EDD];
            float pw[NSS];
            powers16(rv, pw);
            #pragma unroll
            for (int n = 0; n < NSS; n++)
                h[n] = fmaf(pw[n], h[n], pv*S[t][RKK + n]);
            rprod *= rv;
        }
        float pw[NSS];
        powers16(rprod, pw);
        #pragma unroll
        for (int n = 0; n < NSS; n++) {
            g_aP[ob + (size_t)n*EDD] = pw[n];
            g_bL[ob + (size_t)n*EDD] = h[n];
        }
    } else {
        float msum = 0.0f;
        for (int t = 0; t < CHL; t++) {
            float raw = dtbe;
            #pragma unroll
            for (int k = 0; k < RKK; k++) raw = fmaf(S[t][k], wreg[k], raw);
            float dlt, rv;
            softplus_rd(raw, dlt, rv);
            float pv = dlt * xp[(size_t)t*EDD];
            float ml = -dlt;
            msum += ml;
            #pragma unroll
            for (int n = 0; n < NSS; n++) {
                float dA = __expf(a[n]*ml);
                h[n] = fmaf(dA, h[n], pv*S[t][RKK + n]);
            }
        }
        #pragma unroll
        for (int n = 0; n < NSS; n++) {
            g_aP[ob + (size_t)n*EDD] = __expf(a[n]*msum);
            g_bL[ob + (size_t)n*EDD] = h[n];
        }
    }

    __syncthreads();
    if (threadIdx.x == 0) {
        __threadfence();
        atomicExch(&flg[c], target);
    }
    if (threadIdx.x == 0) {
        for (int cc = 0; cc < c; cc++) {
            while (atomicAdd(&flg[cc], 0u) != target) __nanosleep(64);
        }
    }
    __syncthreads();
    __threadfence();

    #pragma unroll
    for (int n = 0; n < NSS; n++) h[n] = 0.0f;
    for (int cc = 0; cc < c; cc++) {
        size_t obc = ((size_t)(b*NCH + cc)*NSS)*EDD + e;
        #pragma unroll
        for (int n = 0; n < NSS; n++) {
            float ap = g_aP[obc + (size_t)n*EDD];
            float bl = g_bL[obc + (size_t)n*EDD];
            h[n] = fmaf(ap, h[n], bl);
        }
    }

    float dp = Dp[e];
    const float* zp = g_xz + ((size_t)(b*LL + c*CHL))*(2*EDD) + EDD + e;
    float*       yp = g_y  + ((size_t)(b*LL + c*CHL))*EDD + e;
    if (fast) {
        for (int t = 0; t < CHL; t++) {
            float raw = dtbe;
            #pragma unroll
            for (int k = 0; k < RKK; k++) raw = fmaf(S[t][k], wreg[k], raw);
            float dlt, rv;
            softplus_rd(raw, dlt, rv);
            float xv = xp[(size_t)t*EDD];
            float zv = zp[(size_t)t*(2*EDD)];
            float pv = dlt * xv;
            float yacc = dp * xv;
            float pw[NSS];
            powers16(rv, pw);
            #pragma unroll
            for (int n = 0; n < NSS; n++) {
                h[n] = fmaf(pw[n], h[n], pv*S[t][RKK + n]);
                yacc = fmaf(h[n], S[t][RKK + NSS + n], yacc);
            }
            float sg = 1.0f/(1.0f + __expf(-zv));
            yp[(size_t)t*EDD] = rtf(yacc * (zv * sg));
        }
    } else {
        for (int t = 0; t < CHL; t++) {
            float raw = dtbe;
            #pragma unroll
            for (int k = 0; k < RKK; k++) raw = fmaf(S[t][k], wreg[k], raw);
            float dlt, rv;
            softplus_rd(raw, dlt, rv);
            float xv = xp[(size_t)t*EDD];
            float zv = zp[(size_t)t*(2*EDD)];
            float pv = dlt * xv;
            float ml = -dlt;
            float yacc = dp * xv;
            #pragma unroll
            for (int n = 0; n < NSS; n++) {
                float dA = __expf(a[n]*ml);
                h[n] = fmaf(dA, h[n], pv*S[t][RKK + n]);
                yacc = fmaf(h[n], S[t][RKK + NSS + n], yacc);
            }
            float sg = 1.0f/(1.0f + __expf(-zv));
            yp[(size_t)t*EDD] = rtf(yacc * (zv * sg));
        }
    }
}

// ---------------- launcher ----------------
extern "C" void kernel_launch(void* const* d_in, const int* in_sizes, int n_in,
                              void* d_out, int out_size)
{
    const int*   tokens    = (const int*)  d_in[0];
    const float* T         = (const float*)d_in[1];
    const float* tok_embed = (const float*)d_in[2];
    const float* pos_embed = (const float*)d_in[3];
    const float* tw1       = (const float*)d_in[4];
    const float* tb1       = (const float*)d_in[5];
    const float* tw2       = (const float*)d_in[6];
    const float* tb2       = (const float*)d_in[7];
    const float* ag        = (const float*)d_in[8];
    const float* ab        = (const float*)d_in[9];
    const float* apw       = (const float*)d_in[10];
    const float* apb       = (const float*)d_in[11];
    const float* in_w      = (const float*)d_in[12];
    const float* conv_w    = (const float*)d_in[13];
    const float* conv_b    = (const float*)d_in[14];
    const float* xp_w      = (const float*)d_in[15];
    const float* dt_w      = (const float*)d_in[16];
    const float* dt_b      = (const float*)d_in[17];
    const float* A_log     = (const float*)d_in[18];
    const float* Dp        = (const float*)d_in[19];
    const float* out_w     = (const float*)d_in[20];
    const float* fg        = (const float*)d_in[21];
    const float* fb        = (const float*)d_in[22];
    const float* hw        = (const float*)d_in[23];
    const float* hb        = (const float*)d_in[24];
    float* out = (float*)d_out;

    float *px, *pxn, *pxz, *pxs, *py, *pxd, *pss, *pwI, *pwX, *pwO;
    cudaGetSymbolAddress((void**)&px,  g_x);
    cudaGetSymbolAddress((void**)&pxn, g_xn);
    cudaGetSymbolAddress((void**)&pxz, g_xz);
    cudaGetSymbolAddress((void**)&pxs, g_xs);
    cudaGetSymbolAddress((void**)&py,  g_y);
    cudaGetSymbolAddress((void**)&pxd, g_xd);
    cudaGetSymbolAddress((void**)&pss, g_ss);
    cudaGetSymbolAddress((void**)&pwI, g_wrI);
    cudaGetSymbolAddress((void**)&pwX, g_wrX);
    cudaGetSymbolAddress((void**)&pwO, g_wrO);

    const int SM_IN = (2*128*36 + 2*32*132) * 4;   // 70656 B
    const int SM_XD = (2*64*36  + 2*32*68)  * 4;   // 35840 B
    cudaFuncSetAttribute((const void*)gemm_tf32p<128,128,32,2,4>,
                         cudaFuncAttributeMaxDynamicSharedMemorySize, SM_IN);
    cudaFuncSetAttribute((const void*)gemm_outf,
                         cudaFuncAttributeMaxDynamicSharedMemorySize, SM_IN);

    k_prologue<<<PRO_EMB + PRO_RND + PRO_CSS, 256>>>(
        tokens, tok_embed, pos_embed, in_w, xp_w, out_w,
        T, tw1, tb1, tw2, tb2, apw, apb);

    for (int i = 0; i < NLY; i++) {
        if (i == 0)
            k_ln<<<BL/4, 256>>>(px, ag, ab, pss, pxn);
        // xz = xn @ in_w[i]   (8192x1024, K=256)
        gemm_tf32p<128,128,32,2,4><<<dim3(2*EDD/128, BL/128), 256, SM_IN>>>(
            pxn, pwI + (size_t)i*DMD*2*EDD, pxz, BL, 2*EDD, DMD, 2*EDD, 0);
        k_conv<<<((BL/4)*EDD + 255)/256, 256>>>(conv_w + (size_t)i*EDD*DCC,
                                                conv_b + (size_t)i*EDD);
        // xd = xs @ xp_w[i]   (8192x48->64, K=512)
        gemm_tf32p<64,64,32,2,2><<<dim3(1, BL/64), 128, SM_XD>>>(
            pxs, pwX + (size_t)i*EDD*NXP, pxd, BL, NXP, EDD, XDS, 0);
        // fused chunked selective scan
        k_scanF<<<dim3(EG, NCH, BB), 128>>>(A_log + (size_t)i*EDD*NSS,
                                            dt_w + (size_t)i*RKK*EDD,
                                            dt_b + (size_t)i*EDD,
                                            Dp + (size_t)i*EDD, i);
        // x += y @ out_w[i] with fused LN epilogue (AdaLN for next layer, or final LN+head)
        int ip1 = (i + 1 < NLY) ? i + 1 : 0;
        gemm_outf<<<dim3(DMD/128, BL/128), 256, SM_IN>>>(
            py, pwO + (size_t)i*EDD*DMD, px, pxn,
            pss + (size_t)ip1*BB*2*DMD, ag + (size_t)ip1*DMD, ab + (size_t)ip1*DMD,
            fg, fb, hw, hb, out, (i < NLY-1) ? 1 : 2);
    }
}

// round 16
// speedup vs baseline: 1.5177x; 1.5177x over previous
#include <cuda_runtime.h>
#include <mma.h>
#include <math.h>
#include <stdint.h>

using namespace nvcuda;

// ---------------- problem constants ----------------
#define BB   8
#define LL   1024
#define DMD  256
#define NLY  4
#define EDD  512
#define NSS  16
#define DCC  4
#define RKK  16
#define CDD  64
#define QQ   2
#define BL   (BB*LL)          // 8192 rows
#define NCH  16               // scan chunks
#define CHL  (LL/NCH)         // 64 steps per chunk
#define XDS  64               // padded row stride of xd buffer (48 -> 64)
#define NXP  48               // xp_w cols
#define EG   (EDD/128)        // e-groups per scan kernel = 4

// ---------------- scratch ----------------
__device__ __align__(256) float g_x [BL*DMD];
__device__ __align__(256) float g_xn[BL*DMD];
__device__ __align__(256) float g_xz[BL*2*EDD];
__device__ __align__(256) float g_xs[BL*EDD];
__device__ __align__(256) float g_y [BL*EDD];
__device__ __align__(256) float g_xd[BL*XDS];
__device__ __align__(256) float g_ss[NLY*BB*2*DMD];
__device__ __align__(256) float g_aP[BB*NCH*NSS*EDD];
__device__ __align__(256) float g_bL[BB*NCH*NSS*EDD];
// tf32-pre-rounded weight copies
__device__ __align__(256) float g_wrI[NLY*DMD*2*EDD];
__device__ __align__(256) float g_wrX[NLY*EDD*NXP];
__device__ __align__(256) float g_wrO[NLY*EDD*DMD];
// scan handshake
__device__ unsigned int g_epoch = 0;
__device__ unsigned int g_sflag[EG*BB*NCH];   // per (g,b,c)

// ---------------- cp.async helpers ----------------
__device__ __forceinline__ void cp16(void* smem_dst, const void* gsrc, int src_bytes)
{
    uint32_t d = (uint32_t)__cvta_generic_to_shared(smem_dst);
    asm volatile("cp.async.cg.shared.global [%0], [%1], 16, %2;\n"
                 :: "r"(d), "l"(gsrc), "r"(src_bytes));
}
__device__ __forceinline__ void cp_commit() { asm volatile("cp.async.commit_group;\n"); }
template<int NG> __device__ __forceinline__ void cp_wait()
{ asm volatile("cp.async.wait_group %0;\n" :: "n"(NG)); }

__device__ __forceinline__ float rtf(float x) { return wmma::__float_to_tf32(x); }

// rv^(n+1) for n=0..15, log-depth
__device__ __forceinline__ void powers16(float rv, float* pw)
{
    pw[0] = rv;
    pw[1] = rv*rv;
    pw[2] = pw[1]*rv;
    pw[3] = pw[1]*pw[1];
    pw[4] = pw[3]*pw[0];
    pw[5] = pw[3]*pw[1];
    pw[6] = pw[3]*pw[2];
    pw[7] = pw[3]*pw[3];
    #pragma unroll
    for (int n = 0; n < 7; n++) pw[8+n] = pw[7]*pw[n];
    pw[15] = pw[7]*pw[7];
}

__device__ __forceinline__ void softplus_rd(float raw, float& dlt, float& rv)
{
    if (raw > 15.0f) { dlt = raw; rv = __expf(-raw); }
    else {
        float ex = __expf(raw);
        rv  = 1.0f/(1.0f + ex);
        dlt = log1pf(ex);
    }
}

// ---------------- prologue: weight rounding + embed + cond/modulation (one kernel) ----------------
#define PRO_EMB  (BL*DMD/256)          // 8192 blocks
#define PRO_RND  1024
#define PRO_CSS  (NLY*BB*2*DMD/256)    // 64 blocks
__global__ void k_prologue(const int* __restrict__ tokens,
                           const float* __restrict__ tok_embed,
                           const float* __restrict__ pos_embed,
                           const float* __restrict__ in_w,
                           const float* __restrict__ xp_w,
                           const float* __restrict__ out_w,
                           const float* __restrict__ T,
                           const float* __restrict__ tw1, const float* __restrict__ tb1,
                           const float* __restrict__ tw2, const float* __restrict__ tb2,
                           const float* __restrict__ apw, const float* __restrict__ apb)
{
    int bid = blockIdx.x;
    int tid = threadIdx.x;
    if (bid < PRO_EMB) {
        int idx = bid*256 + tid;
        int d  = idx % DMD;
        int bl = idx / DMD;
        int l  = bl % LL;
        int b  = bl / LL;
        float v = pos_embed[l*DMD + d];
        if (l > 0) {
            int tok = tokens[b*LL + l - 1];
            v += tok_embed[tok*DMD + d];
        }
        g_x[idx] = v;
        return;
    }
    if (bid < PRO_EMB + PRO_RND) {
        int rb = bid - PRO_EMB;
        if (rb == 0 && tid == 0) atomicAdd(&g_epoch, 1u);
        const int nI = NLY*DMD*2*EDD;
        const int nX = NLY*EDD*NXP;
        const int nO = NLY*EDD*DMD;
        int stride = PRO_RND*256;
        int t0 = rb*256 + tid;
        for (int i = t0; i < nI; i += stride) g_wrI[i] = rtf(in_w[i]);
        for (int i = t0; i < nX; i += stride) g_wrX[i] = rtf(xp_w[i]);
        for (int i = t0; i < nO; i += stride) g_wrO[i] = rtf(out_w[i]);
        return;
    }
    // cond + ss
    __shared__ float hs[BB*CDD];
    __shared__ float cond[BB*CDD];
    #pragma unroll
    for (int q = 0; q < 2; q++) {
        int i2 = tid + q*256;
        int b = i2 / CDD, c = i2 % CDD;
        float u = T[b]*tw1[c] + tb1[c];
        hs[i2] = 0.5f*u*(1.0f + erff(u*0.70710678118654752440f));
    }
    __syncthreads();
    #pragma unroll
    for (int q = 0; q < 2; q++) {
        int i2 = tid + q*256;
        int b = i2 / CDD, c = i2 % CDD;
        float acc = tb2[c];
        #pragma unroll 8
        for (int k = 0; k < CDD; k++) acc += hs[b*CDD + k]*tw2[k*CDD + c];
        cond[i2] = acc;
    }
    __syncthreads();
    int idx = (bid - PRO_EMB - PRO_RND)*256 + tid;   // 0..16383
    int j  = idx % (2*DMD);
    int ib = idx / (2*DMD);
    int b  = ib % BB;
    int i  = ib / BB;
    float acc = apb[i*2*DMD + j];
    #pragma unroll 8
    for (int c = 0; c < CDD; c++)
        acc += cond[b*CDD + c] * apw[((size_t)i*CDD + c)*2*DMD + j];
    g_ss[((size_t)i*BB + b)*2*DMD + j] = acc;
}

// ---------------- AdaLN, tf32-rounded output ----------------
__global__ void k_ln(const float* __restrict__ x, const float* __restrict__ gam,
                     const float* __restrict__ bet, const float* __restrict__ ss,
                     float* __restrict__ out)
{
    int tid = threadIdx.x;              // 256
    int rl  = tid >> 6;
    int lw  = tid & 63;
    int row = blockIdx.x*4 + rl;
    float4 v = reinterpret_cast<const float4*>(x + (size_t)row*DMD)[lw];
    float s  = v.x+v.y+v.z+v.w;
    float s2 = v.x*v.x+v.y*v.y+v.z*v.z+v.w*v.w;
    #pragma unroll
    for (int o = 16; o; o >>= 1) {
        s  += __shfl_xor_sync(0xffffffffu, s,  o);
        s2 += __shfl_xor_sync(0xffffffffu, s2, o);
    }
    __shared__ float sh1[4][2], sh2[4][2];
    if ((lw & 31) == 0) { sh1[rl][lw>>5] = s; sh2[rl][lw>>5] = s2; }
    __syncthreads();
    float tot  = sh1[rl][0] + sh1[rl][1];
    float tot2 = sh2[rl][0] + sh2[rl][1];
    float mean = tot * (1.0f/DMD);
    float var  = tot2 * (1.0f/DMD) - mean*mean;
    float inv  = rsqrtf(var + 1e-5f);
    float4 g  = reinterpret_cast<const float4*>(gam)[lw];
    float4 bb = reinterpret_cast<const float4*>(bet)[lw];
    float4 o4;
    o4.x = (v.x-mean)*inv*g.x + bb.x;
    o4.y = (v.y-mean)*inv*g.y + bb.y;
    o4.z = (v.z-mean)*inv*g.z + bb.z;
    o4.w = (v.w-mean)*inv*g.w + bb.w;
    int b = row / LL;
    float4 sc = reinterpret_cast<const float4*>(ss + (size_t)b*2*DMD)[lw];
    float4 sh = reinterpret_cast<const float4*>(ss + (size_t)b*2*DMD + DMD)[lw];
    o4.x = rtf(fmaf(sc.x, o4.x, o4.x) + sh.x);
    o4.y = rtf(fmaf(sc.y, o4.y, o4.y) + sh.y);
    o4.z = rtf(fmaf(sc.z, o4.z, o4.z) + sh.z);
    o4.w = rtf(fmaf(sc.w, o4.w, o4.w) + sh.w);
    reinterpret_cast<float4*>(out + (size_t)row*DMD)[lw] = o4;
}

// ---------------- fused final LN + head ----------------
__global__ void k_lnhead(const float* __restrict__ x,  const float* __restrict__ fg,
                         const float* __restrict__ fb, const float* __restrict__ hw,
                         const float* __restrict__ hb, float* __restrict__ out)
{
    int tid = threadIdx.x;              // 256
    int rl  = tid >> 6;
    int lw  = tid & 63;
    int row = blockIdx.x*4 + rl;
    float4 v = reinterpret_cast<const float4*>(x + (size_t)row*DMD)[lw];
    float s  = v.x+v.y+v.z+v.w;
    float s2 = v.x*v.x+v.y*v.y+v.z*v.z+v.w*v.w;
    #pragma unroll
    for (int o = 16; o; o >>= 1) {
        s  += __shfl_xor_sync(0xffffffffu, s,  o);
        s2 += __shfl_xor_sync(0xffffffffu, s2, o);
    }
    __shared__ float sh1[4][2], sh2[4][2];
    if ((lw & 31) == 0) { sh1[rl][lw>>5] = s; sh2[rl][lw>>5] = s2; }
    __syncthreads();
    float mean = (sh1[rl][0] + sh1[rl][1]) * (1.0f/DMD);
    float var  = (sh2[rl][0] + sh2[rl][1]) * (1.0f/DMD) - mean*mean;
    float inv  = rsqrtf(var + 1e-5f);
    float4 g  = reinterpret_cast<const float4*>(fg)[lw];
    float4 bb = reinterpret_cast<const float4*>(fb)[lw];
    float o0 = (v.x-mean)*inv*g.x + bb.x;
    float o1 = (v.y-mean)*inv*g.y + bb.y;
    float o2 = (v.z-mean)*inv*g.z + bb.z;
    float o3 = (v.w-mean)*inv*g.w + bb.w;
    const float2* hw2 = reinterpret_cast<const float2*>(hw);
    int d0 = lw*4;
    float2 w0 = hw2[d0+0], w1 = hw2[d0+1], w2 = hw2[d0+2], w3 = hw2[d0+3];
    float p0 = o0*w0.x + o1*w1.x + o2*w2.x + o3*w3.x;
    float p1 = o0*w0.y + o1*w1.y + o2*w2.y + o3*w3.y;
    #pragma unroll
    for (int o = 16; o; o >>= 1) {
        p0 += __shfl_xor_sync(0xffffffffu, p0, o);
        p1 += __shfl_xor_sync(0xffffffffu, p1, o);
    }
    __shared__ float r0[4][2], r1[4][2];
    if ((lw & 31) == 0) { r0[rl][lw>>5] = p0; r1[rl][lw>>5] = p1; }
    __syncthreads();
    if (lw == 0) {
        out[(size_t)row*QQ + 0] = r0[rl][0] + r0[rl][1] + hb[0];
        out[(size_t)row*QQ + 1] = r1[rl][0] + r1[rl][1] + hb[1];
    }
}

// ---------------- pipelined TF32 GEMM (R8 config, inputs pre-rounded) ----------------
template<int BM, int BN, int BK, int WR, int WC>
__global__ void __launch_bounds__(WR*WC*32)
gemm_tf32p(const float* __restrict__ A, const float* __restrict__ W,
           float* __restrict__ C, int M, int Nw, int K, int ldc, int accum)
{
    constexpr int NT  = WR*WC*32;
    constexpr int WM  = BM/WR, WN = BN/WC;
    constexpr int MI  = WM/16, NI = WN/16;
    constexpr int LDA = BK + 4;
    constexpr int LDB = BN + 4;
    extern __shared__ float sm[];
    float* sA = sm;
    float* sB = sm + 2*BM*LDA;

    const int tid  = threadIdx.x;
    const int warp = tid >> 5;
    const int wy   = warp / WC;
    const int wx   = warp % WC;
    const int row0 = blockIdx.y * BM;
    const int col0 = blockIdx.x * BN;

    wmma::fragment<wmma::accumulator, 16,16,8, float> acc[MI][NI];
    #pragma unroll
    for (int i = 0; i < MI; i++)
        #pragma unroll
        for (int j = 0; j < NI; j++) wmma::fill_fragment(acc[i][j], 0.0f);

    auto load_tiles = [&](int st, int k0) {
        float* dA = sA + st*BM*LDA;
        float* dB = sB + st*BK*LDB;
        #pragma unroll
        for (int f = tid; f < BM*(BK/4); f += NT) {
            int r = f / (BK/4);
            int c = (f % (BK/4)) * 4;
            cp16(&dA[r*LDA + c], A + (size_t)(row0+r)*K + k0 + c, 16);
        }
        #pragma unroll
        for (int f = tid; f < BK*(BN/4); f += NT) {
            int r = f / (BN/4);
            int c = (f % (BN/4)) * 4;
            int col = col0 + c;
            int sb  = (col < Nw) ? 16 : 0;
            const float* src = W + (size_t)(k0+r)*Nw + (sb ? col : 0);
            cp16(&dB[r*LDB + c], src, sb);
        }
    };

    const int nt = K / BK;
    int stage = 0;
    load_tiles(0, 0);
    cp_commit();

    for (int t = 0; t < nt; t++) {
        if (t + 1 < nt) {
            load_tiles(stage ^ 1, (t+1)*BK);
            cp_commit();
            cp_wait<1>();
        } else {
            cp_wait<0>();
        }
        __syncthreads();
        const float* cA = sA + stage*BM*LDA;
        const float* cB = sB + stage*BK*LDB;
        #pragma unroll
        for (int kk = 0; kk < BK/8; kk++) {
            wmma::fragment<wmma::matrix_a, 16,16,8, wmma::precision::tf32, wmma::row_major> af[MI];
            wmma::fragment<wmma::matrix_b, 16,16,8, wmma::precision::tf32, wmma::row_major> bf[NI];
            #pragma unroll
            for (int i = 0; i < MI; i++)
                wmma::load_matrix_sync(af[i], &cA[(wy*WM + i*16)*LDA + kk*8], LDA);
            #pragma unroll
            for (int j = 0; j < NI; j++)
                wmma::load_matrix_sync(bf[j], &cB[(kk*8)*LDB + wx*WN + j*16], LDB);
            #pragma unroll
            for (int i = 0; i < MI; i++)
                #pragma unroll
                for (int j = 0; j < NI; j++)
                    wmma::mma_sync(acc[i][j], af[i], bf[j], acc[i][j]);
        }
        __syncthreads();
        stage ^= 1;
    }

    #pragma unroll
    for (int i = 0; i < MI; i++) {
        #pragma unroll
        for (int j = 0; j < NI; j++) {
            float* cptr = C + (size_t)(row0 + wy*WM + i*16)*ldc + col0 + wx*WN + j*16;
            if (accum) {
                wmma::fragment<wmma::accumulator, 16,16,8, float> o;
                wmma::load_matrix_sync(o, cptr, ldc, wmma::mem_row_major);
                #pragma unroll
                for (int e = 0; e < o.num_elements; e++) acc[i][j].x[e] += o.x[e];
            }
            wmma::store_matrix_sync(cptr, acc[i][j], ldc, wmma::mem_row_major);
        }
    }
}

// ---------------- depthwise causal conv + bias + silu, 4 timesteps/thread ----------------
__global__ void k_conv(const float* __restrict__ w, const float* __restrict__ cb)
{
    int idx = blockIdx.x*256 + threadIdx.x;         // (BL/4)*ED
    if (idx >= (BL/4)*EDD) return;
    int e  = idx % EDD;
    int g  = idx / EDD;
    int b  = g / (LL/4);
    int l0 = (g % (LL/4)) * 4;
    size_t bl0 = (size_t)(b*LL + l0);
    const float* base = g_xz + bl0*(2*EDD) + e;
    float4 wv = *reinterpret_cast<const float4*>(w + (size_t)e*DCC);
    float cbe = cb[e];
    float v[7];
    #pragma unroll
    for (int j = 0; j < 3; j++)
        v[j] = (l0 + j >= 3) ? base[(j-3)*(2*EDD)] : 0.0f;
    #pragma unroll
    for (int j = 3; j < 7; j++)
        v[j] = base[(j-3)*(2*EDD)];
    float* outp = g_xs + bl0*EDD + e;
    #pragma unroll
    for (int i = 0; i < 4; i++) {
        float acc = cbe + wv.x*v[i] + wv.y*v[i+1] + wv.z*v[i+2] + wv.w*v[i+3];
        float sg = 1.0f/(1.0f + __expf(-acc));
        outp[(size_t)i*EDD] = rtf(acc * sg);
    }
}

// ---------------- fused scan: summary + flag + prefix combine + replay ----------------
__global__ void k_scanF(const float* __restrict__ Alog, const float* __restrict__ dtw,
                        const float* __restrict__ dtb,  const float* __restrict__ Dp,
                        int layer)
{
    int g = blockIdx.x;
    int c = blockIdx.y;
    int b = blockIdx.z;
    int e = g*128 + threadIdx.x;
    __shared__ float S[CHL][48];
    for (int f = threadIdx.x; f < CHL*12; f += 128) {
        int t = f / 12, q = (f % 12)*4;
        *reinterpret_cast<float4*>(&S[t][q]) =
            *reinterpret_cast<const float4*>(&g_xd[((size_t)(b*LL + c*CHL + t))*XDS + q]);
    }
    float wreg[RKK];
    #pragma unroll
    for (int k = 0; k < RKK; k++) wreg[k] = dtw[(size_t)k*EDD + e];
    float dtbe = dtb[e];
    float a[NSS];
    bool fast = true;
    #pragma unroll
    for (int n = 0; n < NSS; n++) {
        a[n] = expf(Alog[(size_t)e*NSS + n]);
        if (fabsf(a[n] - (float)(n+1)) > 1e-4f*(float)(n+1)) fast = false;
    }
    unsigned int target = (g_epoch - 1u)*NLY + (unsigned)layer + 1u;
    unsigned int* flg = &g_sflag[(g*BB + b)*NCH];
    __syncthreads();

    const float* xp = g_xs + ((size_t)(b*LL + c*CHL))*EDD + e;
    size_t ob = ((size_t)(b*NCH + c)*NSS)*EDD + e;

    float h[NSS];
    #pragma unroll
    for (int n = 0; n < NSS; n++) h[n] = 0.0f;
    if (fast) {
        float rprod = 1.0f;
        for (int t = 0; t < CHL; t++) {
            float raw = dtbe;
            #pragma unroll
            for (int k = 0; k < RKK; k++) raw = fmaf(S[t][k], wreg[k], raw);
            float dlt, rv;
            softplus_rd(raw, dlt, rv);
            float pv = dlt * xp[(size_t)t*EDD];
            float pw[NSS];
            powers16(rv, pw);
            #pragma unroll
            for (int n = 0; n < NSS; n++)
                h[n] = fmaf(pw[n], h[n], pv*S[t][RKK + n]);
            rprod *= rv;
        }
        float pw[NSS];
        powers16(rprod, pw);
        #pragma unroll
        for (int n = 0; n < NSS; n++) {
            g_aP[ob + (size_t)n*EDD] = pw[n];
            g_bL[ob + (size_t)n*EDD] = h[n];
        }
    } else {
        float msum = 0.0f;
        for (int t = 0; t < CHL; t++) {
            float raw = dtbe;
            #pragma unroll
            for (int k = 0; k < RKK; k++) raw = fmaf(S[t][k], wreg[k], raw);
            float dlt, rv;
            softplus_rd(raw, dlt, rv);
            float pv = dlt * xp[(size_t)t*EDD];
            float ml = -dlt;
            msum += ml;
            #pragma unroll
            for (int n = 0; n < NSS; n++) {
                float dA = __expf(a[n]*ml);
                h[n] = fmaf(dA, h[n], pv*S[t][RKK + n]);
            }
        }
        #pragma unroll
        for (int n = 0; n < NSS; n++) {
            g_aP[ob + (size_t)n*EDD] = __expf(a[n]*msum);
            g_bL[ob + (size_t)n*EDD] = h[n];
        }
    }

    __syncthreads();
    if (threadIdx.x == 0) {
        __threadfence();
        atomicExch(&flg[c], target);
    }
    if (threadIdx.x == 0) {
        for (int cc = 0; cc < c; cc++) {
            while (atomicAdd(&flg[cc], 0u) != target) __nanosleep(64);
        }
    }
    __syncthreads();
    __threadfence();

    #pragma unroll
    for (int n = 0; n < NSS; n++) h[n] = 0.0f;
    for (int cc = 0; cc < c; cc++) {
        size_t obc = ((size_t)(b*NCH + cc)*NSS)*EDD + e;
        #pragma unroll
        for (int n = 0; n < NSS; n++) {
            float ap = g_aP[obc + (size_t)n*EDD];
            float bl = g_bL[obc + (size_t)n*EDD];
            h[n] = fmaf(ap, h[n], bl);
        }
    }

    float dp = Dp[e];
    const float* zp = g_xz + ((size_t)(b*LL + c*CHL))*(2*EDD) + EDD + e;
    float*       yp = g_y  + ((size_t)(b*LL + c*CHL))*EDD + e;
    if (fast) {
        for (int t = 0; t < CHL; t++) {
            float raw = dtbe;
            #pragma unroll
            for (int k = 0; k < RKK; k++) raw = fmaf(S[t][k], wreg[k], raw);
            float dlt, rv;
            softplus_rd(raw, dlt, rv);
            float xv = xp[(size_t)t*EDD];
            float zv = zp[(size_t)t*(2*EDD)];
            float pv = dlt * xv;
            float yacc = dp * xv;
            float pw[NSS];
            powers16(rv, pw);
            #pragma unroll
            for (int n = 0; n < NSS; n++) {
                h[n] = fmaf(pw[n], h[n], pv*S[t][RKK + n]);
                yacc = fmaf(h[n], S[t][RKK + NSS + n], yacc);
            }
            float sg = 1.0f/(1.0f + __expf(-zv));
            yp[(size_t)t*EDD] = rtf(yacc * (zv * sg));
        }
    } else {
        for (int t = 0; t < CHL; t++) {
            float raw = dtbe;
            #pragma unroll
            for (int k = 0; k < RKK; k++) raw = fmaf(S[t][k], wreg[k], raw);
            float dlt, rv;
            softplus_rd(raw, dlt, rv);
            float xv = xp[(size_t)t*EDD];
            float zv = zp[(size_t)t*(2*EDD)];
            float pv = dlt * xv;
            float ml = -dlt;
            float yacc = dp * xv;
            #pragma unroll
            for (int n = 0; n < NSS; n++) {
                float dA = __expf(a[n]*ml);
                h[n] = fmaf(dA, h[n], pv*S[t][RKK + n]);
                yacc = fmaf(h[n], S[t][RKK + NSS + n], yacc);
            }
            float sg = 1.0f/(1.0f + __expf(-zv));
            yp[(size_t)t*EDD] = rtf(yacc * (zv * sg));
        }
    }
}

// ---------------- launcher ----------------
extern "C" void kernel_launch(void* const* d_in, const int* in_sizes, int n_in,
                              void* d_out, int out_size)
{
    const int*   tokens    = (const int*)  d_in[0];
    const float* T         = (const float*)d_in[1];
    const float* tok_embed = (const float*)d_in[2];
    const float* pos_embed = (const float*)d_in[3];
    const float* tw1       = (const float*)d_in[4];
    const float* tb1       = (const float*)d_in[5];
    const float* tw2       = (const float*)d_in[6];
    const float* tb2       = (const float*)d_in[7];
    const float* ag        = (const float*)d_in[8];
    const float* ab        = (const float*)d_in[9];
    const float* apw       = (const float*)d_in[10];
    const float* apb       = (const float*)d_in[11];
    const float* in_w      = (const float*)d_in[12];
    const float* conv_w    = (const float*)d_in[13];
    const float* conv_b    = (const float*)d_in[14];
    const float* xp_w      = (const float*)d_in[15];
    const float* dt_w      = (const float*)d_in[16];
    const float* dt_b      = (const float*)d_in[17];
    const float* A_log     = (const float*)d_in[18];
    const float* Dp        = (const float*)d_in[19];
    const float* out_w     = (const float*)d_in[20];
    const float* fg        = (const float*)d_in[21];
    const float* fb        = (const float*)d_in[22];
    const float* hw        = (const float*)d_in[23];
    const float* hb        = (const float*)d_in[24];
    float* out = (float*)d_out;

    float *px, *pxn, *pxz, *pxs, *py, *pxd, *pss, *pwI, *pwX, *pwO;
    cudaGetSymbolAddress((void**)&px,  g_x);
    cudaGetSymbolAddress((void**)&pxn, g_xn);
    cudaGetSymbolAddress((void**)&pxz, g_xz);
    cudaGetSymbolAddress((void**)&pxs, g_xs);
    cudaGetSymbolAddress((void**)&py,  g_y);
    cudaGetSymbolAddress((void**)&pxd, g_xd);
    cudaGetSymbolAddress((void**)&pss, g_ss);
    cudaGetSymbolAddress((void**)&pwI, g_wrI);
    cudaGetSymbolAddress((void**)&pwX, g_wrX);
    cudaGetSymbolAddress((void**)&pwO, g_wrO);

    const int SM_IN = (2*128*36 + 2*32*132) * 4;   // 70656 B
    const int SM_XD = (2*64*36  + 2*32*68)  * 4;   // 35840 B
    cudaFuncSetAttribute((const void*)gemm_tf32p<128,128,32,2,4>,
                         cudaFuncAttributeMaxDynamicSharedMemorySize, SM_IN);

    k_prologue<<<PRO_EMB + PRO_RND + PRO_CSS, 256>>>(
        tokens, tok_embed, pos_embed, in_w, xp_w, out_w,
        T, tw1, tb1, tw2, tb2, apw, apb);

    for (int i = 0; i < NLY; i++) {
        k_ln<<<BL/4, 256>>>(px, ag + (size_t)i*DMD, ab + (size_t)i*DMD,
                            pss + (size_t)i*BB*2*DMD, pxn);
        // xz = xn @ in_w[i]   (8192x1024, K=256)
        gemm_tf32p<128,128,32,2,4><<<dim3(2*EDD/128, BL/128), 256, SM_IN>>>(
            pxn, pwI + (size_t)i*DMD*2*EDD, pxz, BL, 2*EDD, DMD, 2*EDD, 0);
        k_conv<<<((BL/4)*EDD + 255)/256, 256>>>(conv_w + (size_t)i*EDD*DCC,
                                                conv_b + (size_t)i*EDD);
        // xd = xs @ xp_w[i]   (8192x48->64, K=512)
        gemm_tf32p<64,64,32,2,2><<<dim3(1, BL/64), 128, SM_XD>>>(
            pxs, pwX + (size_t)i*EDD*NXP, pxd, BL, NXP, EDD, XDS, 0);
        // fused chunked selective scan
        k_scanF<<<dim3(EG, NCH, BB), 128>>>(A_log + (size_t)i*EDD*NSS,
                                            dt_w + (size_t)i*RKK*EDD,
                                            dt_b + (size_t)i*EDD,
                                            Dp + (size_t)i*EDD, i);
        // x += y @ out_w[i]   (8192x256, K=512), accumulate
        gemm_tf32p<128,128,32,2,4><<<dim3(DMD/128, BL/128), 256, SM_IN>>>(
            py, pwO + (size_t)i*EDD*DMD, px, BL, DMD, EDD, DMD, 1);
    }

    k_lnhead<<<BL/4, 256>>>(px, fg, fb, hw, hb, out);
}